// round 14
// baseline (speedup 1.0000x reference)
#include <cuda_runtime.h>
#include <cuda_fp16.h>
#include <mma.h>
#include <cstdint>

using namespace nvcuda;

#define NV   50000
#define ME   10000
#define NNZt 1600000
#define D    128

#define NBLK_E ((ME + 1023) / 1024)       // 10
#define NBLK_V ((NV + 1023) / 1024)       // 49
#define PB1    (ME / 8)                   // 1250 pass1 blocks (8 edges/block)
#define PBV    ((NNZt / 4 + 255) / 256)   // 1563 permuteV blocks

// ---------------------------------------------------------------------------
// Static device scratch
// ---------------------------------------------------------------------------
__device__ __half g_Xh[NV * D];       // 12.8 MB  fp16 copy of X
__device__ __half g_Xe[ME * D];       // 2.56 MB  edge means (fp16)
__device__ __half g_Xih[NV * D];      // 12.8 MB  mixed vertex features (fp16)
__device__ int    g_histE[ME];
__device__ int    g_histV[NV];
__device__ int    g_offE[ME];
__device__ int    g_offV[NV];
__device__ int    g_curE[ME];
__device__ int    g_curV[NV];
__device__ int    g_vlistE[NNZt];
__device__ int    g_elistV[NNZt];
__device__ int    g_bsumE[64];
__device__ int    g_bsumV[64];

// ---------------------------------------------------------------------------
// Prep: convert X to fp16 AND zero histograms (fused, R12-proven)
// ---------------------------------------------------------------------------
__global__ void prep_kernel(const float* __restrict__ X) {
    int i = blockIdx.x * blockDim.x + threadIdx.x;
    const int n4 = NV * D / 4;
    if (i < n4) {
        float4 v = __ldg(&reinterpret_cast<const float4*>(X)[i]);
        __half2 h0 = __floats2half2_rn(v.x, v.y);
        __half2 h1 = __floats2half2_rn(v.z, v.w);
        uint2 o;
        o.x = *reinterpret_cast<unsigned*>(&h0);
        o.y = *reinterpret_cast<unsigned*>(&h1);
        reinterpret_cast<uint2*>(g_Xh)[i] = o;
    }
    if (i < ME) g_histE[i] = 0;
    if (i < NV) g_histV[i] = 0;
}

// ---------------------------------------------------------------------------
// Histogram: combined E+V, 4 entries/thread = 8 atomic chains (R4-proven)
// ---------------------------------------------------------------------------
__global__ void hist_kernel(const int* __restrict__ vertex,
                            const int* __restrict__ edges) {
    int i0 = (blockIdx.x * blockDim.x + threadIdx.x) * 4;
    if (i0 >= NNZt) return;
    int4 v4 = __ldg(reinterpret_cast<const int4*>(vertex + i0));
    int4 e4 = __ldg(reinterpret_cast<const int4*>(edges + i0));
    atomicAdd(&g_histE[e4.x], 1); atomicAdd(&g_histE[e4.y], 1);
    atomicAdd(&g_histE[e4.z], 1); atomicAdd(&g_histE[e4.w], 1);
    atomicAdd(&g_histV[v4.x], 1); atomicAdd(&g_histV[v4.y], 1);
    atomicAdd(&g_histV[v4.z], 1); atomicAdd(&g_histV[v4.w], 1);
}

// ---------------------------------------------------------------------------
// Scan phase A: per-block (1024 elems) partial sums (R12-proven).
// ---------------------------------------------------------------------------
__global__ __launch_bounds__(256) void scanA_kernel() {
    int b = blockIdx.x;
    const int* hist; int n, bl; int* bsum;
    if (b < NBLK_E) { hist = g_histE; n = ME; bl = b;          bsum = g_bsumE; }
    else            { hist = g_histV; n = NV; bl = b - NBLK_E; bsum = g_bsumV; }
    int t = threadIdx.x;
    int i0 = bl * 1024 + t * 4;
    int s = 0;
    if (i0 < n) {
        int4 v = *reinterpret_cast<const int4*>(hist + i0);
        s = v.x + v.y + v.z + v.w;
    }
    __shared__ int sm[256];
    sm[t] = s; __syncthreads();
    for (int d = 128; d > 0; d >>= 1) {
        if (t < d) sm[t] += sm[t + d];
        __syncthreads();
    }
    if (t == 0) bsum[bl] = sm[0];
}

// ---------------------------------------------------------------------------
// Scan phase C (scanB fused, R12-proven at ~5.3us).
// ---------------------------------------------------------------------------
__global__ __launch_bounds__(256) void scanC_kernel() {
    int b = blockIdx.x;
    const int* hist; int n, bl; int *off, *cur; const int* bsum;
    if (b < NBLK_E) { hist = g_histE; n = ME; bl = b;          off = g_offE; cur = g_curE; bsum = g_bsumE; }
    else            { hist = g_histV; n = NV; bl = b - NBLK_E; off = g_offV; cur = g_curV; bsum = g_bsumV; }
    int t = threadIdx.x;
    int nblk = (b < NBLK_E) ? NBLK_E : NBLK_V;

    __shared__ int bs[64];
    if (t < 64) bs[t] = (t < nblk) ? bsum[t] : 0;
    __syncthreads();
    for (int d = 1; d < 64; d <<= 1) {
        int x = 0;
        if (t < 64 && t >= d) x = bs[t - d];
        __syncthreads();
        if (t < 64) bs[t] += x;
        __syncthreads();
    }
    int blockoff = (bl > 0) ? bs[bl - 1] : 0;

    int i0 = bl * 1024 + t * 4;
    int4 v = make_int4(0, 0, 0, 0);
    int s = 0;
    if (i0 < n) {
        v = *reinterpret_cast<const int4*>(hist + i0);
        s = v.x + v.y + v.z + v.w;
    }
    __shared__ int sm[256];
    sm[t] = s; __syncthreads();
    for (int d = 1; d < 256; d <<= 1) {
        int x = (t >= d) ? sm[t - d] : 0;
        __syncthreads();
        sm[t] += x;
        __syncthreads();
    }
    if (i0 < n) {
        int run = blockoff + sm[t] - s;  // exclusive prefix
        int4 o;
        o.x = run; run += v.x;
        o.y = run; run += v.y;
        o.z = run; run += v.z;
        o.w = run;
        *reinterpret_cast<int4*>(off + i0) = o;
        *reinterpret_cast<int4*>(cur + i0) = o;
    }
}

// ---------------------------------------------------------------------------
// Permute E-side only: 8 entries/thread = 8 independent atomic+store chains
// (matches the R4-proven 8-chain density; R12 ran this at 4 chains / 39us).
// ---------------------------------------------------------------------------
__global__ void permuteE_kernel(const int* __restrict__ vertex,
                                const int* __restrict__ edges) {
    int i0 = (blockIdx.x * blockDim.x + threadIdx.x) * 8;
    if (i0 >= NNZt) return;
    int4 va = __ldg(reinterpret_cast<const int4*>(vertex + i0));
    int4 vb = __ldg(reinterpret_cast<const int4*>(vertex + i0 + 4));
    int4 ea = __ldg(reinterpret_cast<const int4*>(edges + i0));
    int4 eb = __ldg(reinterpret_cast<const int4*>(edges + i0 + 4));
    int p0 = atomicAdd(&g_curE[ea.x], 1);
    int p1 = atomicAdd(&g_curE[ea.y], 1);
    int p2 = atomicAdd(&g_curE[ea.z], 1);
    int p3 = atomicAdd(&g_curE[ea.w], 1);
    int p4 = atomicAdd(&g_curE[eb.x], 1);
    int p5 = atomicAdd(&g_curE[eb.y], 1);
    int p6 = atomicAdd(&g_curE[eb.z], 1);
    int p7 = atomicAdd(&g_curE[eb.w], 1);
    g_vlistE[p0] = va.x; g_vlistE[p1] = va.y;
    g_vlistE[p2] = va.z; g_vlistE[p3] = va.w;
    g_vlistE[p4] = vb.x; g_vlistE[p5] = vb.y;
    g_vlistE[p6] = vb.z; g_vlistE[p7] = vb.w;
}

// ---------------------------------------------------------------------------
// Fused pass1 + permuteV (R12-proven, block-partitioned):
//   blocks [0, PB1):      pass1 — Xe[e] = mean_v Xh[v]  (warp per edge)
//   blocks [PB1, +PBV):   permuteV — elistV[curV[v]++] = e  (4 chains)
// ---------------------------------------------------------------------------
__global__ __launch_bounds__(256) void pass1_permV_kernel(
    const int* __restrict__ vertex,
    const int* __restrict__ edges) {
    if (blockIdx.x < PB1) {
        int e = blockIdx.x * 8 + (threadIdx.x >> 5);
        int lane = threadIdx.x & 31;
        int beg = g_offE[e];
        int cnt = g_histE[e];
        const uint2* X2 = reinterpret_cast<const uint2*>(g_Xh);

        float4 acc = make_float4(0.f, 0.f, 0.f, 0.f);
        for (int base = 0; base < cnt; base += 32) {
            int m = cnt - base; if (m > 32) m = 32;
            int idx = 0;
            if (base + lane < cnt) idx = __ldg(&g_vlistE[beg + base + lane]);
            if (m == 32) {
#pragma unroll 8
                for (int j = 0; j < 32; j++) {
                    int v = __shfl_sync(0xffffffffu, idx, j);
                    uint2 d = __ldg(&X2[(size_t)v * 32 + lane]);
                    float2 f0 = __half22float2(*reinterpret_cast<__half2*>(&d.x));
                    float2 f1 = __half22float2(*reinterpret_cast<__half2*>(&d.y));
                    acc.x += f0.x; acc.y += f0.y; acc.z += f1.x; acc.w += f1.y;
                }
            } else {
                for (int j = 0; j < m; j++) {
                    int v = __shfl_sync(0xffffffffu, idx, j);
                    uint2 d = __ldg(&X2[(size_t)v * 32 + lane]);
                    float2 f0 = __half22float2(*reinterpret_cast<__half2*>(&d.x));
                    float2 f1 = __half22float2(*reinterpret_cast<__half2*>(&d.y));
                    acc.x += f0.x; acc.y += f0.y; acc.z += f1.x; acc.w += f1.y;
                }
            }
        }
        float s = (cnt > 0) ? 1.0f / (float)cnt : 0.0f;
        __half2 h0 = __floats2half2_rn(acc.x * s, acc.y * s);
        __half2 h1 = __floats2half2_rn(acc.z * s, acc.w * s);
        uint2 o;
        o.x = *reinterpret_cast<unsigned*>(&h0);
        o.y = *reinterpret_cast<unsigned*>(&h1);
        reinterpret_cast<uint2*>(g_Xe)[(size_t)e * 32 + lane] = o;
    } else {
        int i0 = ((blockIdx.x - PB1) * 256 + threadIdx.x) * 4;
        if (i0 >= NNZt) return;
        int4 v4 = __ldg(reinterpret_cast<const int4*>(vertex + i0));
        int4 e4 = __ldg(reinterpret_cast<const int4*>(edges + i0));
        int q0 = atomicAdd(&g_curV[v4.x], 1);
        int q1 = atomicAdd(&g_curV[v4.y], 1);
        int q2 = atomicAdd(&g_curV[v4.z], 1);
        int q3 = atomicAdd(&g_curV[v4.w], 1);
        g_elistV[q0] = e4.x; g_elistV[q1] = e4.y;
        g_elistV[q2] = e4.z; g_elistV[q3] = e4.w;
    }
}

// ---------------------------------------------------------------------------
// Pass 2 (fused mix, R9-proven): Xi[n] = (1-a)*mean_e Xe[e] + a*X0[n], fp16.
// ---------------------------------------------------------------------------
__global__ __launch_bounds__(256) void pass2_kernel(const float* __restrict__ X0,
                                                    const float* __restrict__ pAlpha) {
    int n = blockIdx.x * (blockDim.x >> 5) + (threadIdx.x >> 5);
    if (n >= NV) return;
    int lane = threadIdx.x & 31;
    int beg = g_offV[n];
    int cnt = g_histV[n];
    const uint2* E2 = reinterpret_cast<const uint2*>(g_Xe);

    float4 acc = make_float4(0.f, 0.f, 0.f, 0.f);
    for (int base = 0; base < cnt; base += 32) {
        int m = cnt - base; if (m > 32) m = 32;
        int idx = 0;
        if (base + lane < cnt) idx = __ldg(&g_elistV[beg + base + lane]);
        if (m == 32) {
#pragma unroll 8
            for (int j = 0; j < 32; j++) {
                int e = __shfl_sync(0xffffffffu, idx, j);
                uint2 d = __ldg(&E2[(size_t)e * 32 + lane]);
                float2 f0 = __half22float2(*reinterpret_cast<__half2*>(&d.x));
                float2 f1 = __half22float2(*reinterpret_cast<__half2*>(&d.y));
                acc.x += f0.x; acc.y += f0.y; acc.z += f1.x; acc.w += f1.y;
            }
        } else {
            for (int j = 0; j < m; j++) {
                int e = __shfl_sync(0xffffffffu, idx, j);
                uint2 d = __ldg(&E2[(size_t)e * 32 + lane]);
                float2 f0 = __half22float2(*reinterpret_cast<__half2*>(&d.x));
                float2 f1 = __half22float2(*reinterpret_cast<__half2*>(&d.y));
                acc.x += f0.x; acc.y += f0.y; acc.z += f1.x; acc.w += f1.y;
            }
        }
    }
    float alpha = __ldg(pAlpha);
    float s = (cnt > 0) ? (1.0f - alpha) / (float)cnt : 0.0f;
    float4 x0 = __ldg(&reinterpret_cast<const float4*>(X0)[(size_t)n * 32 + lane]);
    __half2 h0 = __floats2half2_rn(acc.x * s + alpha * x0.x,
                                   acc.y * s + alpha * x0.y);
    __half2 h1 = __floats2half2_rn(acc.z * s + alpha * x0.z,
                                   acc.w * s + alpha * x0.w);
    uint2 o;
    o.x = *reinterpret_cast<unsigned*>(&h0);
    o.y = *reinterpret_cast<unsigned*>(&h1);
    reinterpret_cast<uint2*>(g_Xih)[(size_t)n * 32 + lane] = o;
}

// ---------------------------------------------------------------------------
// Final (HMMA, R7-proven): out = Xi @ Weff^T,  Weff = (1-beta)*I + beta*W.
// ---------------------------------------------------------------------------
#define GR 64

__global__ __launch_bounds__(256) void final_kernel(
    const float* __restrict__ W,
    const float* __restrict__ pBeta,
    float* __restrict__ out) {
    __shared__ __half Ws[D * D];  // Weff[c][k] row-major, 32 KB

    const float beta = __ldg(pBeta);
    const float omb  = 1.0f - beta;
    const int tid = threadIdx.x;

    for (int idx = tid; idx < D * D; idx += 256) {
        int c = idx >> 7;
        int k = idx & 127;
        float w = beta * __ldg(W + idx) + ((c == k) ? omb : 0.0f);
        Ws[idx] = __float2half(w);
    }
    __syncthreads();

    const int warp = tid >> 5;
    const int wrow = warp >> 1;
    const int wcol = (warp & 1) * 4;
    const int row0 = blockIdx.x * GR + wrow * 16;
    if (row0 + 16 > NV) return;

    wmma::fragment<wmma::accumulator, 16, 16, 16, float> c_frag[4];
#pragma unroll
    for (int j = 0; j < 4; j++) wmma::fill_fragment(c_frag[j], 0.0f);

    const __half* A = g_Xih;
#pragma unroll
    for (int k = 0; k < 8; k++) {
        wmma::fragment<wmma::matrix_a, 16, 16, 16, __half, wmma::row_major> a_frag;
        wmma::load_matrix_sync(a_frag, A + (size_t)row0 * D + k * 16, D);
#pragma unroll
        for (int j = 0; j < 4; j++) {
            wmma::fragment<wmma::matrix_b, 16, 16, 16, __half, wmma::col_major> b_frag;
            wmma::load_matrix_sync(b_frag, Ws + (wcol + j) * 16 * D + k * 16, D);
            wmma::mma_sync(c_frag[j], a_frag, b_frag, c_frag[j]);
        }
    }

#pragma unroll
    for (int j = 0; j < 4; j++) {
        wmma::store_matrix_sync(out + (size_t)row0 * D + (wcol + j) * 16,
                                c_frag[j], D, wmma::mem_row_major);
    }
}

// ---------------------------------------------------------------------------
extern "C" void kernel_launch(void* const* d_in, const int* in_sizes, int n_in,
                              void* d_out, int out_size) {
    const float* X      = (const float*)d_in[0];
    const float* X0     = (const float*)d_in[1];
    const float* W      = (const float*)d_in[2];
    const float* pAlpha = (const float*)d_in[3];
    const float* pBeta  = (const float*)d_in[4];
    const int*   vertex = (const int*)d_in[5];
    const int*   edges  = (const int*)d_in[6];
    float* out = (float*)d_out;

    prep_kernel<<<(NV * D / 4 + 255) / 256, 256>>>(X);
    hist_kernel<<<(NNZt / 4 + 255) / 256, 256>>>(vertex, edges);
    scanA_kernel<<<NBLK_E + NBLK_V, 256>>>();
    scanC_kernel<<<NBLK_E + NBLK_V, 256>>>();
    permuteE_kernel<<<(NNZt / 8 + 255) / 256, 256>>>(vertex, edges);

    pass1_permV_kernel<<<PB1 + PBV, 256>>>(vertex, edges);
    pass2_kernel<<<(NV * 32 + 255) / 256, 256>>>(X0, pAlpha);

    final_kernel<<<(NV + GR - 1) / GR, 256>>>(W, pBeta, out);
}

// round 15
// speedup vs baseline: 1.0464x; 1.0464x over previous
#include <cuda_runtime.h>
#include <cuda_fp16.h>
#include <mma.h>
#include <cstdint>

using namespace nvcuda;

#define NV   50000
#define ME   10000
#define NNZt 1600000
#define D    128

#define NBLK_E ((ME + 1023) / 1024)       // 10
#define NBLK_V ((NV + 1023) / 1024)       // 49
#define PB1    (ME / 8)                   // 1250 pass1 blocks (8 edges/block)
#define PBV    ((NNZt / 4 + 255) / 256)   // 1563 permuteV blocks

// ---------------------------------------------------------------------------
// Static device scratch
// ---------------------------------------------------------------------------
__device__ __half g_Xh[NV * D];       // 12.8 MB  fp16 copy of X
__device__ __half g_Xe[ME * D];       // 2.56 MB  edge means (fp16)
__device__ __half g_Xih[NV * D];      // 12.8 MB  mixed vertex features (fp16)
__device__ int    g_histE[ME];
__device__ int    g_histV[NV];
__device__ int    g_offE[ME];
__device__ int    g_offV[NV];
__device__ int    g_curE[ME];
__device__ int    g_curV[NV];
__device__ int    g_vlistE[NNZt];
__device__ int    g_elistV[NNZt];
__device__ int    g_bsumE[64];
__device__ int    g_bsumV[64];

// ---------------------------------------------------------------------------
// Prep: convert X to fp16 AND zero histograms (fused, R12-proven)
// ---------------------------------------------------------------------------
__global__ void prep_kernel(const float* __restrict__ X) {
    int i = blockIdx.x * blockDim.x + threadIdx.x;
    const int n4 = NV * D / 4;
    if (i < n4) {
        float4 v = __ldg(&reinterpret_cast<const float4*>(X)[i]);
        __half2 h0 = __floats2half2_rn(v.x, v.y);
        __half2 h1 = __floats2half2_rn(v.z, v.w);
        uint2 o;
        o.x = *reinterpret_cast<unsigned*>(&h0);
        o.y = *reinterpret_cast<unsigned*>(&h1);
        reinterpret_cast<uint2*>(g_Xh)[i] = o;
    }
    if (i < ME) g_histE[i] = 0;
    if (i < NV) g_histV[i] = 0;
}

// ---------------------------------------------------------------------------
// Histogram: combined E+V, 4 entries/thread = 8 atomic chains (R4-proven)
// ---------------------------------------------------------------------------
__global__ void hist_kernel(const int* __restrict__ vertex,
                            const int* __restrict__ edges) {
    int i0 = (blockIdx.x * blockDim.x + threadIdx.x) * 4;
    if (i0 >= NNZt) return;
    int4 v4 = __ldg(reinterpret_cast<const int4*>(vertex + i0));
    int4 e4 = __ldg(reinterpret_cast<const int4*>(edges + i0));
    atomicAdd(&g_histE[e4.x], 1); atomicAdd(&g_histE[e4.y], 1);
    atomicAdd(&g_histE[e4.z], 1); atomicAdd(&g_histE[e4.w], 1);
    atomicAdd(&g_histV[v4.x], 1); atomicAdd(&g_histV[v4.y], 1);
    atomicAdd(&g_histV[v4.z], 1); atomicAdd(&g_histV[v4.w], 1);
}

// ---------------------------------------------------------------------------
// Scan phase A: per-block (1024 elems) partial sums (R12-proven).
// ---------------------------------------------------------------------------
__global__ __launch_bounds__(256) void scanA_kernel() {
    int b = blockIdx.x;
    const int* hist; int n, bl; int* bsum;
    if (b < NBLK_E) { hist = g_histE; n = ME; bl = b;          bsum = g_bsumE; }
    else            { hist = g_histV; n = NV; bl = b - NBLK_E; bsum = g_bsumV; }
    int t = threadIdx.x;
    int i0 = bl * 1024 + t * 4;
    int s = 0;
    if (i0 < n) {
        int4 v = *reinterpret_cast<const int4*>(hist + i0);
        s = v.x + v.y + v.z + v.w;
    }
    __shared__ int sm[256];
    sm[t] = s; __syncthreads();
    for (int d = 128; d > 0; d >>= 1) {
        if (t < d) sm[t] += sm[t + d];
        __syncthreads();
    }
    if (t == 0) bsum[bl] = sm[0];
}

// ---------------------------------------------------------------------------
// Scan phase C (scanB fused, R12-proven at ~5.3us).
// ---------------------------------------------------------------------------
__global__ __launch_bounds__(256) void scanC_kernel() {
    int b = blockIdx.x;
    const int* hist; int n, bl; int *off, *cur; const int* bsum;
    if (b < NBLK_E) { hist = g_histE; n = ME; bl = b;          off = g_offE; cur = g_curE; bsum = g_bsumE; }
    else            { hist = g_histV; n = NV; bl = b - NBLK_E; off = g_offV; cur = g_curV; bsum = g_bsumV; }
    int t = threadIdx.x;
    int nblk = (b < NBLK_E) ? NBLK_E : NBLK_V;

    __shared__ int bs[64];
    if (t < 64) bs[t] = (t < nblk) ? bsum[t] : 0;
    __syncthreads();
    for (int d = 1; d < 64; d <<= 1) {
        int x = 0;
        if (t < 64 && t >= d) x = bs[t - d];
        __syncthreads();
        if (t < 64) bs[t] += x;
        __syncthreads();
    }
    int blockoff = (bl > 0) ? bs[bl - 1] : 0;

    int i0 = bl * 1024 + t * 4;
    int4 v = make_int4(0, 0, 0, 0);
    int s = 0;
    if (i0 < n) {
        v = *reinterpret_cast<const int4*>(hist + i0);
        s = v.x + v.y + v.z + v.w;
    }
    __shared__ int sm[256];
    sm[t] = s; __syncthreads();
    for (int d = 1; d < 256; d <<= 1) {
        int x = (t >= d) ? sm[t - d] : 0;
        __syncthreads();
        sm[t] += x;
        __syncthreads();
    }
    if (i0 < n) {
        int run = blockoff + sm[t] - s;  // exclusive prefix
        int4 o;
        o.x = run; run += v.x;
        o.y = run; run += v.y;
        o.z = run; run += v.z;
        o.w = run;
        *reinterpret_cast<int4*>(off + i0) = o;
        *reinterpret_cast<int4*>(cur + i0) = o;
    }
}

// ---------------------------------------------------------------------------
// Permute E-side only: 2 entries/thread = 2 atomic chains, max warp count
// (trend across {16,8,4} entries says fewer chains / more warps wins here;
// per-address LTS serialization means deep per-thread MLP just queues).
// ---------------------------------------------------------------------------
__global__ void permuteE_kernel(const int* __restrict__ vertex,
                                const int* __restrict__ edges) {
    int i0 = (blockIdx.x * blockDim.x + threadIdx.x) * 2;
    if (i0 >= NNZt) return;
    int2 v2 = __ldg(reinterpret_cast<const int2*>(vertex + i0));
    int2 e2 = __ldg(reinterpret_cast<const int2*>(edges + i0));
    int p0 = atomicAdd(&g_curE[e2.x], 1);
    int p1 = atomicAdd(&g_curE[e2.y], 1);
    g_vlistE[p0] = v2.x;
    g_vlistE[p1] = v2.y;
}

// ---------------------------------------------------------------------------
// Fused pass1 + permuteV (R12-proven, block-partitioned):
//   blocks [0, PB1):      pass1 — Xe[e] = mean_v Xh[v]  (warp per edge)
//   blocks [PB1, +PBV):   permuteV — elistV[curV[v]++] = e  (4 chains)
// ---------------------------------------------------------------------------
__global__ __launch_bounds__(256) void pass1_permV_kernel(
    const int* __restrict__ vertex,
    const int* __restrict__ edges) {
    if (blockIdx.x < PB1) {
        int e = blockIdx.x * 8 + (threadIdx.x >> 5);
        int lane = threadIdx.x & 31;
        int beg = g_offE[e];
        int cnt = g_histE[e];
        const uint2* X2 = reinterpret_cast<const uint2*>(g_Xh);

        float4 acc = make_float4(0.f, 0.f, 0.f, 0.f);
        for (int base = 0; base < cnt; base += 32) {
            int m = cnt - base; if (m > 32) m = 32;
            int idx = 0;
            if (base + lane < cnt) idx = __ldg(&g_vlistE[beg + base + lane]);
            if (m == 32) {
#pragma unroll 8
                for (int j = 0; j < 32; j++) {
                    int v = __shfl_sync(0xffffffffu, idx, j);
                    uint2 d = __ldg(&X2[(size_t)v * 32 + lane]);
                    float2 f0 = __half22float2(*reinterpret_cast<__half2*>(&d.x));
                    float2 f1 = __half22float2(*reinterpret_cast<__half2*>(&d.y));
                    acc.x += f0.x; acc.y += f0.y; acc.z += f1.x; acc.w += f1.y;
                }
            } else {
                for (int j = 0; j < m; j++) {
                    int v = __shfl_sync(0xffffffffu, idx, j);
                    uint2 d = __ldg(&X2[(size_t)v * 32 + lane]);
                    float2 f0 = __half22float2(*reinterpret_cast<__half2*>(&d.x));
                    float2 f1 = __half22float2(*reinterpret_cast<__half2*>(&d.y));
                    acc.x += f0.x; acc.y += f0.y; acc.z += f1.x; acc.w += f1.y;
                }
            }
        }
        float s = (cnt > 0) ? 1.0f / (float)cnt : 0.0f;
        __half2 h0 = __floats2half2_rn(acc.x * s, acc.y * s);
        __half2 h1 = __floats2half2_rn(acc.z * s, acc.w * s);
        uint2 o;
        o.x = *reinterpret_cast<unsigned*>(&h0);
        o.y = *reinterpret_cast<unsigned*>(&h1);
        reinterpret_cast<uint2*>(g_Xe)[(size_t)e * 32 + lane] = o;
    } else {
        int i0 = ((blockIdx.x - PB1) * 256 + threadIdx.x) * 4;
        if (i0 >= NNZt) return;
        int4 v4 = __ldg(reinterpret_cast<const int4*>(vertex + i0));
        int4 e4 = __ldg(reinterpret_cast<const int4*>(edges + i0));
        int q0 = atomicAdd(&g_curV[v4.x], 1);
        int q1 = atomicAdd(&g_curV[v4.y], 1);
        int q2 = atomicAdd(&g_curV[v4.z], 1);
        int q3 = atomicAdd(&g_curV[v4.w], 1);
        g_elistV[q0] = e4.x; g_elistV[q1] = e4.y;
        g_elistV[q2] = e4.z; g_elistV[q3] = e4.w;
    }
}

// ---------------------------------------------------------------------------
// Pass 2 (fused mix, R9-proven): Xi[n] = (1-a)*mean_e Xe[e] + a*X0[n], fp16.
// ---------------------------------------------------------------------------
__global__ __launch_bounds__(256) void pass2_kernel(const float* __restrict__ X0,
                                                    const float* __restrict__ pAlpha) {
    int n = blockIdx.x * (blockDim.x >> 5) + (threadIdx.x >> 5);
    if (n >= NV) return;
    int lane = threadIdx.x & 31;
    int beg = g_offV[n];
    int cnt = g_histV[n];
    const uint2* E2 = reinterpret_cast<const uint2*>(g_Xe);

    float4 acc = make_float4(0.f, 0.f, 0.f, 0.f);
    for (int base = 0; base < cnt; base += 32) {
        int m = cnt - base; if (m > 32) m = 32;
        int idx = 0;
        if (base + lane < cnt) idx = __ldg(&g_elistV[beg + base + lane]);
        if (m == 32) {
#pragma unroll 8
            for (int j = 0; j < 32; j++) {
                int e = __shfl_sync(0xffffffffu, idx, j);
                uint2 d = __ldg(&E2[(size_t)e * 32 + lane]);
                float2 f0 = __half22float2(*reinterpret_cast<__half2*>(&d.x));
                float2 f1 = __half22float2(*reinterpret_cast<__half2*>(&d.y));
                acc.x += f0.x; acc.y += f0.y; acc.z += f1.x; acc.w += f1.y;
            }
        } else {
            for (int j = 0; j < m; j++) {
                int e = __shfl_sync(0xffffffffu, idx, j);
                uint2 d = __ldg(&E2[(size_t)e * 32 + lane]);
                float2 f0 = __half22float2(*reinterpret_cast<__half2*>(&d.x));
                float2 f1 = __half22float2(*reinterpret_cast<__half2*>(&d.y));
                acc.x += f0.x; acc.y += f0.y; acc.z += f1.x; acc.w += f1.y;
            }
        }
    }
    float alpha = __ldg(pAlpha);
    float s = (cnt > 0) ? (1.0f - alpha) / (float)cnt : 0.0f;
    float4 x0 = __ldg(&reinterpret_cast<const float4*>(X0)[(size_t)n * 32 + lane]);
    __half2 h0 = __floats2half2_rn(acc.x * s + alpha * x0.x,
                                   acc.y * s + alpha * x0.y);
    __half2 h1 = __floats2half2_rn(acc.z * s + alpha * x0.z,
                                   acc.w * s + alpha * x0.w);
    uint2 o;
    o.x = *reinterpret_cast<unsigned*>(&h0);
    o.y = *reinterpret_cast<unsigned*>(&h1);
    reinterpret_cast<uint2*>(g_Xih)[(size_t)n * 32 + lane] = o;
}

// ---------------------------------------------------------------------------
// Final (HMMA, R7-proven): out = Xi @ Weff^T,  Weff = (1-beta)*I + beta*W.
// ---------------------------------------------------------------------------
#define GR 64

__global__ __launch_bounds__(256) void final_kernel(
    const float* __restrict__ W,
    const float* __restrict__ pBeta,
    float* __restrict__ out) {
    __shared__ __half Ws[D * D];  // Weff[c][k] row-major, 32 KB

    const float beta = __ldg(pBeta);
    const float omb  = 1.0f - beta;
    const int tid = threadIdx.x;

    for (int idx = tid; idx < D * D; idx += 256) {
        int c = idx >> 7;
        int k = idx & 127;
        float w = beta * __ldg(W + idx) + ((c == k) ? omb : 0.0f);
        Ws[idx] = __float2half(w);
    }
    __syncthreads();

    const int warp = tid >> 5;
    const int wrow = warp >> 1;
    const int wcol = (warp & 1) * 4;
    const int row0 = blockIdx.x * GR + wrow * 16;
    if (row0 + 16 > NV) return;

    wmma::fragment<wmma::accumulator, 16, 16, 16, float> c_frag[4];
#pragma unroll
    for (int j = 0; j < 4; j++) wmma::fill_fragment(c_frag[j], 0.0f);

    const __half* A = g_Xih;
#pragma unroll
    for (int k = 0; k < 8; k++) {
        wmma::fragment<wmma::matrix_a, 16, 16, 16, __half, wmma::row_major> a_frag;
        wmma::load_matrix_sync(a_frag, A + (size_t)row0 * D + k * 16, D);
#pragma unroll
        for (int j = 0; j < 4; j++) {
            wmma::fragment<wmma::matrix_b, 16, 16, 16, __half, wmma::col_major> b_frag;
            wmma::load_matrix_sync(b_frag, Ws + (wcol + j) * 16 * D + k * 16, D);
            wmma::mma_sync(c_frag[j], a_frag, b_frag, c_frag[j]);
        }
    }

#pragma unroll
    for (int j = 0; j < 4; j++) {
        wmma::store_matrix_sync(out + (size_t)row0 * D + (wcol + j) * 16,
                                c_frag[j], D, wmma::mem_row_major);
    }
}

// ---------------------------------------------------------------------------
extern "C" void kernel_launch(void* const* d_in, const int* in_sizes, int n_in,
                              void* d_out, int out_size) {
    const float* X      = (const float*)d_in[0];
    const float* X0     = (const float*)d_in[1];
    const float* W      = (const float*)d_in[2];
    const float* pAlpha = (const float*)d_in[3];
    const float* pBeta  = (const float*)d_in[4];
    const int*   vertex = (const int*)d_in[5];
    const int*   edges  = (const int*)d_in[6];
    float* out = (float*)d_out;

    prep_kernel<<<(NV * D / 4 + 255) / 256, 256>>>(X);
    hist_kernel<<<(NNZt / 4 + 255) / 256, 256>>>(vertex, edges);
    scanA_kernel<<<NBLK_E + NBLK_V, 256>>>();
    scanC_kernel<<<NBLK_E + NBLK_V, 256>>>();
    permuteE_kernel<<<(NNZt / 2 + 255) / 256, 256>>>(vertex, edges);

    pass1_permV_kernel<<<PB1 + PBV, 256>>>(vertex, edges);
    pass2_kernel<<<(NV * 32 + 255) / 256, 256>>>(X0, pAlpha);

    final_kernel<<<(NV + GR - 1) / GR, 256>>>(W, pBeta, out);
}

// round 16
// speedup vs baseline: 1.1458x; 1.0950x over previous
#include <cuda_runtime.h>
#include <cuda_fp16.h>
#include <mma.h>
#include <cstdint>

using namespace nvcuda;

#define NV   50000
#define ME   10000
#define NNZt 1600000
#define D    128

#define NBLK_E ((ME + 1023) / 1024)       // 10
#define NBLK_V ((NV + 1023) / 1024)       // 49
#define PB1    (ME / 8)                   // 1250 pass1 blocks (8 edges/block)
#define PBV    ((NNZt / 4 + 255) / 256)   // 1563 permuteV blocks

// ---------------------------------------------------------------------------
// Static device scratch
// ---------------------------------------------------------------------------
__device__ __half g_Xh[NV * D];       // 12.8 MB  fp16 copy of X
__device__ __half g_Xe[ME * D];       // 2.56 MB  edge means (fp16)
__device__ __half g_Xih[NV * D];      // 12.8 MB  mixed vertex features (fp16)
__device__ int    g_histE[ME];
__device__ int    g_histV[NV];
__device__ int    g_offE[ME];
__device__ int    g_offV[NV];
__device__ int    g_vlistE[NNZt];
__device__ int    g_elistV[NNZt];
__device__ int    g_bsumE[64];
__device__ int    g_bsumV[64];
__device__ unsigned short g_rankE[NNZt];  // 3.2 MB  rank of entry within its edge
__device__ unsigned short g_rankV[NNZt];  // 3.2 MB  rank of entry within its vertex

// ---------------------------------------------------------------------------
// Prep: convert X to fp16 AND zero histograms (fused, R12-proven)
// ---------------------------------------------------------------------------
__global__ void prep_kernel(const float* __restrict__ X) {
    int i = blockIdx.x * blockDim.x + threadIdx.x;
    const int n4 = NV * D / 4;
    if (i < n4) {
        float4 v = __ldg(&reinterpret_cast<const float4*>(X)[i]);
        __half2 h0 = __floats2half2_rn(v.x, v.y);
        __half2 h1 = __floats2half2_rn(v.z, v.w);
        uint2 o;
        o.x = *reinterpret_cast<unsigned*>(&h0);
        o.y = *reinterpret_cast<unsigned*>(&h1);
        reinterpret_cast<uint2*>(g_Xh)[i] = o;
    }
    if (i < ME) g_histE[i] = 0;
    if (i < NV) g_histV[i] = 0;
}

// ---------------------------------------------------------------------------
// Histogram + rank capture: the atomicAdd return value IS each entry's rank
// within its edge/vertex group — store it (ushort4, coalesced) so the permute
// passes need no atomics at all.
// ---------------------------------------------------------------------------
__global__ void hist_kernel(const int* __restrict__ vertex,
                            const int* __restrict__ edges) {
    int i0 = (blockIdx.x * blockDim.x + threadIdx.x) * 4;
    if (i0 >= NNZt) return;
    int4 v4 = __ldg(reinterpret_cast<const int4*>(vertex + i0));
    int4 e4 = __ldg(reinterpret_cast<const int4*>(edges + i0));
    int re0 = atomicAdd(&g_histE[e4.x], 1);
    int re1 = atomicAdd(&g_histE[e4.y], 1);
    int re2 = atomicAdd(&g_histE[e4.z], 1);
    int re3 = atomicAdd(&g_histE[e4.w], 1);
    int rv0 = atomicAdd(&g_histV[v4.x], 1);
    int rv1 = atomicAdd(&g_histV[v4.y], 1);
    int rv2 = atomicAdd(&g_histV[v4.z], 1);
    int rv3 = atomicAdd(&g_histV[v4.w], 1);
    ushort4 re = make_ushort4((unsigned short)re0, (unsigned short)re1,
                              (unsigned short)re2, (unsigned short)re3);
    ushort4 rv = make_ushort4((unsigned short)rv0, (unsigned short)rv1,
                              (unsigned short)rv2, (unsigned short)rv3);
    *reinterpret_cast<ushort4*>(g_rankE + i0) = re;
    *reinterpret_cast<ushort4*>(g_rankV + i0) = rv;
}

// ---------------------------------------------------------------------------
// Scan phase A: per-block (1024 elems) partial sums (R12-proven).
// ---------------------------------------------------------------------------
__global__ __launch_bounds__(256) void scanA_kernel() {
    int b = blockIdx.x;
    const int* hist; int n, bl; int* bsum;
    if (b < NBLK_E) { hist = g_histE; n = ME; bl = b;          bsum = g_bsumE; }
    else            { hist = g_histV; n = NV; bl = b - NBLK_E; bsum = g_bsumV; }
    int t = threadIdx.x;
    int i0 = bl * 1024 + t * 4;
    int s = 0;
    if (i0 < n) {
        int4 v = *reinterpret_cast<const int4*>(hist + i0);
        s = v.x + v.y + v.z + v.w;
    }
    __shared__ int sm[256];
    sm[t] = s; __syncthreads();
    for (int d = 128; d > 0; d >>= 1) {
        if (t < d) sm[t] += sm[t + d];
        __syncthreads();
    }
    if (t == 0) bsum[bl] = sm[0];
}

// ---------------------------------------------------------------------------
// Scan phase C (scanB fused, R12-proven): writes off only (cur eliminated).
// ---------------------------------------------------------------------------
__global__ __launch_bounds__(256) void scanC_kernel() {
    int b = blockIdx.x;
    const int* hist; int n, bl; int *off; const int* bsum;
    if (b < NBLK_E) { hist = g_histE; n = ME; bl = b;          off = g_offE; bsum = g_bsumE; }
    else            { hist = g_histV; n = NV; bl = b - NBLK_E; off = g_offV; bsum = g_bsumV; }
    int t = threadIdx.x;
    int nblk = (b < NBLK_E) ? NBLK_E : NBLK_V;

    __shared__ int bs[64];
    if (t < 64) bs[t] = (t < nblk) ? bsum[t] : 0;
    __syncthreads();
    for (int d = 1; d < 64; d <<= 1) {
        int x = 0;
        if (t < 64 && t >= d) x = bs[t - d];
        __syncthreads();
        if (t < 64) bs[t] += x;
        __syncthreads();
    }
    int blockoff = (bl > 0) ? bs[bl - 1] : 0;

    int i0 = bl * 1024 + t * 4;
    int4 v = make_int4(0, 0, 0, 0);
    int s = 0;
    if (i0 < n) {
        v = *reinterpret_cast<const int4*>(hist + i0);
        s = v.x + v.y + v.z + v.w;
    }
    __shared__ int sm[256];
    sm[t] = s; __syncthreads();
    for (int d = 1; d < 256; d <<= 1) {
        int x = (t >= d) ? sm[t - d] : 0;
        __syncthreads();
        sm[t] += x;
        __syncthreads();
    }
    if (i0 < n) {
        int run = blockoff + sm[t] - s;  // exclusive prefix
        int4 o;
        o.x = run; run += v.x;
        o.y = run; run += v.y;
        o.z = run; run += v.z;
        o.w = run;
        *reinterpret_cast<int4*>(off + i0) = o;
    }
}

// ---------------------------------------------------------------------------
// Permute E-side, ATOMIC-FREE: slot = offE[e] + rankE[i] (rank captured in
// hist). Pure loads + fire-and-forget scattered stores.
// ---------------------------------------------------------------------------
__global__ void permuteE_kernel(const int* __restrict__ vertex,
                                const int* __restrict__ edges) {
    int i0 = (blockIdx.x * blockDim.x + threadIdx.x) * 4;
    if (i0 >= NNZt) return;
    int4 v4 = __ldg(reinterpret_cast<const int4*>(vertex + i0));
    int4 e4 = __ldg(reinterpret_cast<const int4*>(edges + i0));
    ushort4 r = *reinterpret_cast<const ushort4*>(g_rankE + i0);
    g_vlistE[__ldg(&g_offE[e4.x]) + r.x] = v4.x;
    g_vlistE[__ldg(&g_offE[e4.y]) + r.y] = v4.y;
    g_vlistE[__ldg(&g_offE[e4.z]) + r.z] = v4.z;
    g_vlistE[__ldg(&g_offE[e4.w]) + r.w] = v4.w;
}

// ---------------------------------------------------------------------------
// Fused pass1 + permuteV (R12-proven partition; permV now atomic-free):
//   blocks [0, PB1):      pass1 — Xe[e] = mean_v Xh[v]  (warp per edge)
//   blocks [PB1, +PBV):   permuteV — elistV[offV[v] + rankV[i]] = e
// ---------------------------------------------------------------------------
__global__ __launch_bounds__(256) void pass1_permV_kernel(
    const int* __restrict__ vertex,
    const int* __restrict__ edges) {
    if (blockIdx.x < PB1) {
        int e = blockIdx.x * 8 + (threadIdx.x >> 5);
        int lane = threadIdx.x & 31;
        int beg = g_offE[e];
        int cnt = g_histE[e];
        const uint2* X2 = reinterpret_cast<const uint2*>(g_Xh);

        float4 acc = make_float4(0.f, 0.f, 0.f, 0.f);
        for (int base = 0; base < cnt; base += 32) {
            int m = cnt - base; if (m > 32) m = 32;
            int idx = 0;
            if (base + lane < cnt) idx = __ldg(&g_vlistE[beg + base + lane]);
            if (m == 32) {
#pragma unroll 8
                for (int j = 0; j < 32; j++) {
                    int v = __shfl_sync(0xffffffffu, idx, j);
                    uint2 d = __ldg(&X2[(size_t)v * 32 + lane]);
                    float2 f0 = __half22float2(*reinterpret_cast<__half2*>(&d.x));
                    float2 f1 = __half22float2(*reinterpret_cast<__half2*>(&d.y));
                    acc.x += f0.x; acc.y += f0.y; acc.z += f1.x; acc.w += f1.y;
                }
            } else {
                for (int j = 0; j < m; j++) {
                    int v = __shfl_sync(0xffffffffu, idx, j);
                    uint2 d = __ldg(&X2[(size_t)v * 32 + lane]);
                    float2 f0 = __half22float2(*reinterpret_cast<__half2*>(&d.x));
                    float2 f1 = __half22float2(*reinterpret_cast<__half2*>(&d.y));
                    acc.x += f0.x; acc.y += f0.y; acc.z += f1.x; acc.w += f1.y;
                }
            }
        }
        float s = (cnt > 0) ? 1.0f / (float)cnt : 0.0f;
        __half2 h0 = __floats2half2_rn(acc.x * s, acc.y * s);
        __half2 h1 = __floats2half2_rn(acc.z * s, acc.w * s);
        uint2 o;
        o.x = *reinterpret_cast<unsigned*>(&h0);
        o.y = *reinterpret_cast<unsigned*>(&h1);
        reinterpret_cast<uint2*>(g_Xe)[(size_t)e * 32 + lane] = o;
    } else {
        int i0 = ((blockIdx.x - PB1) * 256 + threadIdx.x) * 4;
        if (i0 >= NNZt) return;
        int4 v4 = __ldg(reinterpret_cast<const int4*>(vertex + i0));
        int4 e4 = __ldg(reinterpret_cast<const int4*>(edges + i0));
        ushort4 r = *reinterpret_cast<const ushort4*>(g_rankV + i0);
        g_elistV[__ldg(&g_offV[v4.x]) + r.x] = e4.x;
        g_elistV[__ldg(&g_offV[v4.y]) + r.y] = e4.y;
        g_elistV[__ldg(&g_offV[v4.z]) + r.z] = e4.z;
        g_elistV[__ldg(&g_offV[v4.w]) + r.w] = e4.w;
    }
}

// ---------------------------------------------------------------------------
// Pass 2 (fused mix, R9-proven): Xi[n] = (1-a)*mean_e Xe[e] + a*X0[n], fp16.
// ---------------------------------------------------------------------------
__global__ __launch_bounds__(256) void pass2_kernel(const float* __restrict__ X0,
                                                    const float* __restrict__ pAlpha) {
    int n = blockIdx.x * (blockDim.x >> 5) + (threadIdx.x >> 5);
    if (n >= NV) return;
    int lane = threadIdx.x & 31;
    int beg = g_offV[n];
    int cnt = g_histV[n];
    const uint2* E2 = reinterpret_cast<const uint2*>(g_Xe);

    float4 acc = make_float4(0.f, 0.f, 0.f, 0.f);
    for (int base = 0; base < cnt; base += 32) {
        int m = cnt - base; if (m > 32) m = 32;
        int idx = 0;
        if (base + lane < cnt) idx = __ldg(&g_elistV[beg + base + lane]);
        if (m == 32) {
#pragma unroll 8
            for (int j = 0; j < 32; j++) {
                int e = __shfl_sync(0xffffffffu, idx, j);
                uint2 d = __ldg(&E2[(size_t)e * 32 + lane]);
                float2 f0 = __half22float2(*reinterpret_cast<__half2*>(&d.x));
                float2 f1 = __half22float2(*reinterpret_cast<__half2*>(&d.y));
                acc.x += f0.x; acc.y += f0.y; acc.z += f1.x; acc.w += f1.y;
            }
        } else {
            for (int j = 0; j < m; j++) {
                int e = __shfl_sync(0xffffffffu, idx, j);
                uint2 d = __ldg(&E2[(size_t)e * 32 + lane]);
                float2 f0 = __half22float2(*reinterpret_cast<__half2*>(&d.x));
                float2 f1 = __half22float2(*reinterpret_cast<__half2*>(&d.y));
                acc.x += f0.x; acc.y += f0.y; acc.z += f1.x; acc.w += f1.y;
            }
        }
    }
    float alpha = __ldg(pAlpha);
    float s = (cnt > 0) ? (1.0f - alpha) / (float)cnt : 0.0f;
    float4 x0 = __ldg(&reinterpret_cast<const float4*>(X0)[(size_t)n * 32 + lane]);
    __half2 h0 = __floats2half2_rn(acc.x * s + alpha * x0.x,
                                   acc.y * s + alpha * x0.y);
    __half2 h1 = __floats2half2_rn(acc.z * s + alpha * x0.z,
                                   acc.w * s + alpha * x0.w);
    uint2 o;
    o.x = *reinterpret_cast<unsigned*>(&h0);
    o.y = *reinterpret_cast<unsigned*>(&h1);
    reinterpret_cast<uint2*>(g_Xih)[(size_t)n * 32 + lane] = o;
}

// ---------------------------------------------------------------------------
// Final (HMMA, R7-proven): out = Xi @ Weff^T,  Weff = (1-beta)*I + beta*W.
// ---------------------------------------------------------------------------
#define GR 64

__global__ __launch_bounds__(256) void final_kernel(
    const float* __restrict__ W,
    const float* __restrict__ pBeta,
    float* __restrict__ out) {
    __shared__ __half Ws[D * D];  // Weff[c][k] row-major, 32 KB

    const float beta = __ldg(pBeta);
    const float omb  = 1.0f - beta;
    const int tid = threadIdx.x;

    for (int idx = tid; idx < D * D; idx += 256) {
        int c = idx >> 7;
        int k = idx & 127;
        float w = beta * __ldg(W + idx) + ((c == k) ? omb : 0.0f);
        Ws[idx] = __float2half(w);
    }
    __syncthreads();

    const int warp = tid >> 5;
    const int wrow = warp >> 1;
    const int wcol = (warp & 1) * 4;
    const int row0 = blockIdx.x * GR + wrow * 16;
    if (row0 + 16 > NV) return;

    wmma::fragment<wmma::accumulator, 16, 16, 16, float> c_frag[4];
#pragma unroll
    for (int j = 0; j < 4; j++) wmma::fill_fragment(c_frag[j], 0.0f);

    const __half* A = g_Xih;
#pragma unroll
    for (int k = 0; k < 8; k++) {
        wmma::fragment<wmma::matrix_a, 16, 16, 16, __half, wmma::row_major> a_frag;
        wmma::load_matrix_sync(a_frag, A + (size_t)row0 * D + k * 16, D);
#pragma unroll
        for (int j = 0; j < 4; j++) {
            wmma::fragment<wmma::matrix_b, 16, 16, 16, __half, wmma::col_major> b_frag;
            wmma::load_matrix_sync(b_frag, Ws + (wcol + j) * 16 * D + k * 16, D);
            wmma::mma_sync(c_frag[j], a_frag, b_frag, c_frag[j]);
        }
    }

#pragma unroll
    for (int j = 0; j < 4; j++) {
        wmma::store_matrix_sync(out + (size_t)row0 * D + (wcol + j) * 16,
                                c_frag[j], D, wmma::mem_row_major);
    }
}

// ---------------------------------------------------------------------------
extern "C" void kernel_launch(void* const* d_in, const int* in_sizes, int n_in,
                              void* d_out, int out_size) {
    const float* X      = (const float*)d_in[0];
    const float* X0     = (const float*)d_in[1];
    const float* W      = (const float*)d_in[2];
    const float* pAlpha = (const float*)d_in[3];
    const float* pBeta  = (const float*)d_in[4];
    const int*   vertex = (const int*)d_in[5];
    const int*   edges  = (const int*)d_in[6];
    float* out = (float*)d_out;

    prep_kernel<<<(NV * D / 4 + 255) / 256, 256>>>(X);
    hist_kernel<<<(NNZt / 4 + 255) / 256, 256>>>(vertex, edges);
    scanA_kernel<<<NBLK_E + NBLK_V, 256>>>();
    scanC_kernel<<<NBLK_E + NBLK_V, 256>>>();
    permuteE_kernel<<<(NNZt / 4 + 255) / 256, 256>>>(vertex, edges);

    pass1_permV_kernel<<<PB1 + PBV, 256>>>(vertex, edges);
    pass2_kernel<<<(NV * 32 + 255) / 256, 256>>>(X0, pAlpha);

    final_kernel<<<(NV + GR - 1) / GR, 256>>>(W, pBeta, out);
}

// round 17
// speedup vs baseline: 1.1546x; 1.0077x over previous
#include <cuda_runtime.h>
#include <cuda_fp16.h>
#include <mma.h>
#include <cstdint>

using namespace nvcuda;

#define NV   50000
#define ME   10000
#define NNZt 1600000
#define D    128

#define NBLK_E ((ME + 1023) / 1024)       // 10
#define NBLK_V ((NV + 1023) / 1024)       // 49
#define SCB    (NBLK_E + NBLK_V)          // 59 scan blocks
#define CVB    ((NV * D / 4 + 255) / 256) // 6250 convert blocks
#define PB1    (ME / 8)                   // 1250 pass1 blocks (8 edges/block)
#define PBV    ((NNZt / 4 + 255) / 256)   // 1563 permuteV blocks

// ---------------------------------------------------------------------------
// Static device scratch
// ---------------------------------------------------------------------------
__device__ __half g_Xh[NV * D];       // 12.8 MB  fp16 copy of X
__device__ __half g_Xe[ME * D];       // 2.56 MB  edge means (fp16)
__device__ __half g_Xih[NV * D];      // 12.8 MB  mixed vertex features (fp16)
__device__ int    g_histE[ME];
__device__ int    g_histV[NV];
__device__ int    g_offE[ME];
__device__ int    g_offV[NV];
__device__ int    g_vlistE[NNZt];
__device__ int    g_elistV[NNZt];
__device__ unsigned short g_rankE[NNZt];  // 3.2 MB  rank within edge group
__device__ unsigned short g_rankV[NNZt];  // 3.2 MB  rank within vertex group

// ---------------------------------------------------------------------------
// Zero histograms (tiny, must precede hist)
// ---------------------------------------------------------------------------
__global__ void zero_hist_kernel() {
    int i = blockIdx.x * blockDim.x + threadIdx.x;
    if (i < ME / 4) reinterpret_cast<int4*>(g_histE)[i] = make_int4(0, 0, 0, 0);
    if (i < NV / 4) reinterpret_cast<int4*>(g_histV)[i] = make_int4(0, 0, 0, 0);
}

// ---------------------------------------------------------------------------
// Histogram + rank capture (R16-proven): atomicAdd return value IS the rank.
// ---------------------------------------------------------------------------
__global__ void hist_kernel(const int* __restrict__ vertex,
                            const int* __restrict__ edges) {
    int i0 = (blockIdx.x * blockDim.x + threadIdx.x) * 4;
    if (i0 >= NNZt) return;
    int4 v4 = __ldg(reinterpret_cast<const int4*>(vertex + i0));
    int4 e4 = __ldg(reinterpret_cast<const int4*>(edges + i0));
    int re0 = atomicAdd(&g_histE[e4.x], 1);
    int re1 = atomicAdd(&g_histE[e4.y], 1);
    int re2 = atomicAdd(&g_histE[e4.z], 1);
    int re3 = atomicAdd(&g_histE[e4.w], 1);
    int rv0 = atomicAdd(&g_histV[v4.x], 1);
    int rv1 = atomicAdd(&g_histV[v4.y], 1);
    int rv2 = atomicAdd(&g_histV[v4.z], 1);
    int rv3 = atomicAdd(&g_histV[v4.w], 1);
    ushort4 re = make_ushort4((unsigned short)re0, (unsigned short)re1,
                              (unsigned short)re2, (unsigned short)re3);
    ushort4 rv = make_ushort4((unsigned short)rv0, (unsigned short)rv1,
                              (unsigned short)rv2, (unsigned short)rv3);
    *reinterpret_cast<ushort4*>(g_rankE + i0) = re;
    *reinterpret_cast<ushort4*>(g_rankV + i0) = rv;
}

// ---------------------------------------------------------------------------
// Fused scan + convert (block-partitioned):
//   blocks [0, SCB):      single-pass exclusive scan (R13-validated body:
//                         block self-computes its offset by summing the
//                         preceding hist range, L2-resident), writes off.
//   blocks [SCB, +CVB):   convert X -> fp16 on otherwise-idle SMs.
// ---------------------------------------------------------------------------
__global__ __launch_bounds__(256) void scanAC_convert_kernel(
    const float* __restrict__ X) {
    if (blockIdx.x >= SCB) {
        int i = (blockIdx.x - SCB) * 256 + threadIdx.x;
        const int n4 = NV * D / 4;
        if (i >= n4) return;
        float4 v = __ldg(&reinterpret_cast<const float4*>(X)[i]);
        __half2 h0 = __floats2half2_rn(v.x, v.y);
        __half2 h1 = __floats2half2_rn(v.z, v.w);
        uint2 o;
        o.x = *reinterpret_cast<unsigned*>(&h0);
        o.y = *reinterpret_cast<unsigned*>(&h1);
        reinterpret_cast<uint2*>(g_Xh)[i] = o;
        return;
    }

    int b = blockIdx.x;
    const int* hist; int n, bl; int *off;
    if (b < NBLK_E) { hist = g_histE; n = ME; bl = b;          off = g_offE; }
    else            { hist = g_histV; n = NV; bl = b - NBLK_E; off = g_offV; }
    int t = threadIdx.x;

    // blockoff = sum of hist[0 .. bl*1024)  (coalesced strided int4 reads)
    int lim = bl * 1024;
    int partial = 0;
    for (int i = t * 4; i < lim; i += 1024) {
        int4 v = *reinterpret_cast<const int4*>(hist + i);
        partial += v.x + v.y + v.z + v.w;
    }
    __shared__ int red[256];
    red[t] = partial; __syncthreads();
    for (int d = 128; d > 0; d >>= 1) {
        if (t < d) red[t] += red[t + d];
        __syncthreads();
    }
    int blockoff = red[0];
    __syncthreads();

    // local exclusive prefix over this block's 1024 elements
    int i0 = lim + t * 4;
    int4 v = make_int4(0, 0, 0, 0);
    int s = 0;
    if (i0 < n) {
        v = *reinterpret_cast<const int4*>(hist + i0);
        s = v.x + v.y + v.z + v.w;
    }
    __shared__ int sm[256];
    sm[t] = s; __syncthreads();
    for (int d = 1; d < 256; d <<= 1) {
        int x = (t >= d) ? sm[t - d] : 0;
        __syncthreads();
        sm[t] += x;
        __syncthreads();
    }
    if (i0 < n) {
        int run = blockoff + sm[t] - s;  // exclusive prefix
        int4 o;
        o.x = run; run += v.x;
        o.y = run; run += v.y;
        o.z = run; run += v.z;
        o.w = run;
        *reinterpret_cast<int4*>(off + i0) = o;
    }
}

// ---------------------------------------------------------------------------
// Permute E-side, ATOMIC-FREE (R16-proven): slot = offE[e] + rankE[i].
// ---------------------------------------------------------------------------
__global__ void permuteE_kernel(const int* __restrict__ vertex,
                                const int* __restrict__ edges) {
    int i0 = (blockIdx.x * blockDim.x + threadIdx.x) * 4;
    if (i0 >= NNZt) return;
    int4 v4 = __ldg(reinterpret_cast<const int4*>(vertex + i0));
    int4 e4 = __ldg(reinterpret_cast<const int4*>(edges + i0));
    ushort4 r = *reinterpret_cast<const ushort4*>(g_rankE + i0);
    g_vlistE[__ldg(&g_offE[e4.x]) + r.x] = v4.x;
    g_vlistE[__ldg(&g_offE[e4.y]) + r.y] = v4.y;
    g_vlistE[__ldg(&g_offE[e4.z]) + r.z] = v4.z;
    g_vlistE[__ldg(&g_offE[e4.w]) + r.w] = v4.w;
}

// ---------------------------------------------------------------------------
// Fused pass1 + permuteV (R16-proven):
//   blocks [0, PB1):      pass1 — Xe[e] = mean_v Xh[v]  (warp per edge)
//   blocks [PB1, +PBV):   permuteV — elistV[offV[v] + rankV[i]] = e
// ---------------------------------------------------------------------------
__global__ __launch_bounds__(256) void pass1_permV_kernel(
    const int* __restrict__ vertex,
    const int* __restrict__ edges) {
    if (blockIdx.x < PB1) {
        int e = blockIdx.x * 8 + (threadIdx.x >> 5);
        int lane = threadIdx.x & 31;
        int beg = g_offE[e];
        int cnt = g_histE[e];
        const uint2* X2 = reinterpret_cast<const uint2*>(g_Xh);

        float4 acc = make_float4(0.f, 0.f, 0.f, 0.f);
        for (int base = 0; base < cnt; base += 32) {
            int m = cnt - base; if (m > 32) m = 32;
            int idx = 0;
            if (base + lane < cnt) idx = __ldg(&g_vlistE[beg + base + lane]);
            if (m == 32) {
#pragma unroll 8
                for (int j = 0; j < 32; j++) {
                    int v = __shfl_sync(0xffffffffu, idx, j);
                    uint2 d = __ldg(&X2[(size_t)v * 32 + lane]);
                    float2 f0 = __half22float2(*reinterpret_cast<__half2*>(&d.x));
                    float2 f1 = __half22float2(*reinterpret_cast<__half2*>(&d.y));
                    acc.x += f0.x; acc.y += f0.y; acc.z += f1.x; acc.w += f1.y;
                }
            } else {
                for (int j = 0; j < m; j++) {
                    int v = __shfl_sync(0xffffffffu, idx, j);
                    uint2 d = __ldg(&X2[(size_t)v * 32 + lane]);
                    float2 f0 = __half22float2(*reinterpret_cast<__half2*>(&d.x));
                    float2 f1 = __half22float2(*reinterpret_cast<__half2*>(&d.y));
                    acc.x += f0.x; acc.y += f0.y; acc.z += f1.x; acc.w += f1.y;
                }
            }
        }
        float s = (cnt > 0) ? 1.0f / (float)cnt : 0.0f;
        __half2 h0 = __floats2half2_rn(acc.x * s, acc.y * s);
        __half2 h1 = __floats2half2_rn(acc.z * s, acc.w * s);
        uint2 o;
        o.x = *reinterpret_cast<unsigned*>(&h0);
        o.y = *reinterpret_cast<unsigned*>(&h1);
        reinterpret_cast<uint2*>(g_Xe)[(size_t)e * 32 + lane] = o;
    } else {
        int i0 = ((blockIdx.x - PB1) * 256 + threadIdx.x) * 4;
        if (i0 >= NNZt) return;
        int4 v4 = __ldg(reinterpret_cast<const int4*>(vertex + i0));
        int4 e4 = __ldg(reinterpret_cast<const int4*>(edges + i0));
        ushort4 r = *reinterpret_cast<const ushort4*>(g_rankV + i0);
        g_elistV[__ldg(&g_offV[v4.x]) + r.x] = e4.x;
        g_elistV[__ldg(&g_offV[v4.y]) + r.y] = e4.y;
        g_elistV[__ldg(&g_offV[v4.z]) + r.z] = e4.z;
        g_elistV[__ldg(&g_offV[v4.w]) + r.w] = e4.w;
    }
}

// ---------------------------------------------------------------------------
// Pass 2 (fused mix, R9-proven): Xi[n] = (1-a)*mean_e Xe[e] + a*X0[n], fp16.
// ---------------------------------------------------------------------------
__global__ __launch_bounds__(256) void pass2_kernel(const float* __restrict__ X0,
                                                    const float* __restrict__ pAlpha) {
    int n = blockIdx.x * (blockDim.x >> 5) + (threadIdx.x >> 5);
    if (n >= NV) return;
    int lane = threadIdx.x & 31;
    int beg = g_offV[n];
    int cnt = g_histV[n];
    const uint2* E2 = reinterpret_cast<const uint2*>(g_Xe);

    float4 acc = make_float4(0.f, 0.f, 0.f, 0.f);
    for (int base = 0; base < cnt; base += 32) {
        int m = cnt - base; if (m > 32) m = 32;
        int idx = 0;
        if (base + lane < cnt) idx = __ldg(&g_elistV[beg + base + lane]);
        if (m == 32) {
#pragma unroll 8
            for (int j = 0; j < 32; j++) {
                int e = __shfl_sync(0xffffffffu, idx, j);
                uint2 d = __ldg(&E2[(size_t)e * 32 + lane]);
                float2 f0 = __half22float2(*reinterpret_cast<__half2*>(&d.x));
                float2 f1 = __half22float2(*reinterpret_cast<__half2*>(&d.y));
                acc.x += f0.x; acc.y += f0.y; acc.z += f1.x; acc.w += f1.y;
            }
        } else {
            for (int j = 0; j < m; j++) {
                int e = __shfl_sync(0xffffffffu, idx, j);
                uint2 d = __ldg(&E2[(size_t)e * 32 + lane]);
                float2 f0 = __half22float2(*reinterpret_cast<__half2*>(&d.x));
                float2 f1 = __half22float2(*reinterpret_cast<__half2*>(&d.y));
                acc.x += f0.x; acc.y += f0.y; acc.z += f1.x; acc.w += f1.y;
            }
        }
    }
    float alpha = __ldg(pAlpha);
    float s = (cnt > 0) ? (1.0f - alpha) / (float)cnt : 0.0f;
    float4 x0 = __ldg(&reinterpret_cast<const float4*>(X0)[(size_t)n * 32 + lane]);
    __half2 h0 = __floats2half2_rn(acc.x * s + alpha * x0.x,
                                   acc.y * s + alpha * x0.y);
    __half2 h1 = __floats2half2_rn(acc.z * s + alpha * x0.z,
                                   acc.w * s + alpha * x0.w);
    uint2 o;
    o.x = *reinterpret_cast<unsigned*>(&h0);
    o.y = *reinterpret_cast<unsigned*>(&h1);
    reinterpret_cast<uint2*>(g_Xih)[(size_t)n * 32 + lane] = o;
}

// ---------------------------------------------------------------------------
// Final (HMMA, R7-proven): out = Xi @ Weff^T,  Weff = (1-beta)*I + beta*W.
// ---------------------------------------------------------------------------
#define GR 64

__global__ __launch_bounds__(256) void final_kernel(
    const float* __restrict__ W,
    const float* __restrict__ pBeta,
    float* __restrict__ out) {
    __shared__ __half Ws[D * D];  // Weff[c][k] row-major, 32 KB

    const float beta = __ldg(pBeta);
    const float omb  = 1.0f - beta;
    const int tid = threadIdx.x;

    for (int idx = tid; idx < D * D; idx += 256) {
        int c = idx >> 7;
        int k = idx & 127;
        float w = beta * __ldg(W + idx) + ((c == k) ? omb : 0.0f);
        Ws[idx] = __float2half(w);
    }
    __syncthreads();

    const int warp = tid >> 5;
    const int wrow = warp >> 1;
    const int wcol = (warp & 1) * 4;
    const int row0 = blockIdx.x * GR + wrow * 16;
    if (row0 + 16 > NV) return;

    wmma::fragment<wmma::accumulator, 16, 16, 16, float> c_frag[4];
#pragma unroll
    for (int j = 0; j < 4; j++) wmma::fill_fragment(c_frag[j], 0.0f);

    const __half* A = g_Xih;
#pragma unroll
    for (int k = 0; k < 8; k++) {
        wmma::fragment<wmma::matrix_a, 16, 16, 16, __half, wmma::row_major> a_frag;
        wmma::load_matrix_sync(a_frag, A + (size_t)row0 * D + k * 16, D);
#pragma unroll
        for (int j = 0; j < 4; j++) {
            wmma::fragment<wmma::matrix_b, 16, 16, 16, __half, wmma::col_major> b_frag;
            wmma::load_matrix_sync(b_frag, Ws + (wcol + j) * 16 * D + k * 16, D);
            wmma::mma_sync(c_frag[j], a_frag, b_frag, c_frag[j]);
        }
    }

#pragma unroll
    for (int j = 0; j < 4; j++) {
        wmma::store_matrix_sync(out + (size_t)row0 * D + (wcol + j) * 16,
                                c_frag[j], D, wmma::mem_row_major);
    }
}

// ---------------------------------------------------------------------------
extern "C" void kernel_launch(void* const* d_in, const int* in_sizes, int n_in,
                              void* d_out, int out_size) {
    const float* X      = (const float*)d_in[0];
    const float* X0     = (const float*)d_in[1];
    const float* W      = (const float*)d_in[2];
    const float* pAlpha = (const float*)d_in[3];
    const float* pBeta  = (const float*)d_in[4];
    const int*   vertex = (const int*)d_in[5];
    const int*   edges  = (const int*)d_in[6];
    float* out = (float*)d_out;

    zero_hist_kernel<<<(NV / 4 + 255) / 256, 256>>>();
    hist_kernel<<<(NNZt / 4 + 255) / 256, 256>>>(vertex, edges);
    scanAC_convert_kernel<<<SCB + CVB, 256>>>(X);
    permuteE_kernel<<<(NNZt / 4 + 255) / 256, 256>>>(vertex, edges);

    pass1_permV_kernel<<<PB1 + PBV, 256>>>(vertex, edges);
    pass2_kernel<<<(NV * 32 + 255) / 256, 256>>>(X0, pAlpha);

    final_kernel<<<(NV + GR - 1) / GR, 256>>>(W, pBeta, out);
}